// round 15
// baseline (speedup 1.0000x reference)
#include <cuda_runtime.h>

// Problem constants (from reference: B=128, H=W=256, 68 keypoints)
#define HDIM 256
#define WDIM 256
#define HWSZ (HDIM * WDIM)          // 65536
#define NKPT 68
#define OFFSET_SCALE 6.0f

// Y = inverse(X)^T for row-major 3x3 X. (inv^T = cofactor/det)
__device__ __forceinline__ void inv3_transpose(const float X[9], float Y[9]) {
    float c00 = X[4]*X[8] - X[5]*X[7];
    float c01 = X[5]*X[6] - X[3]*X[8];
    float c02 = X[3]*X[7] - X[4]*X[6];
    float c10 = X[2]*X[7] - X[1]*X[8];
    float c11 = X[0]*X[8] - X[2]*X[6];
    float c12 = X[1]*X[6] - X[0]*X[7];
    float c20 = X[1]*X[5] - X[2]*X[4];
    float c21 = X[2]*X[3] - X[0]*X[5];
    float c22 = X[0]*X[4] - X[1]*X[3];
    float det = X[0]*c00 + X[1]*c01 + X[2]*c02;
    float id  = 1.0f / det;
    Y[0] = c00*id; Y[1] = c01*id; Y[2] = c02*id;
    Y[3] = c10*id; Y[4] = c11*id; Y[5] = c12*id;
    Y[6] = c20*id; Y[7] = c21*id; Y[8] = c22*id;
}

__device__ __forceinline__ float warp_sum(float v) {
    #pragma unroll
    for (int off = 16; off > 0; off >>= 1)
        v += __shfl_xor_sync(0xFFFFFFFFu, v, off);
    return v;
}

// ONE fused kernel. 32 blocks per batch, 256 threads.
// Each block redundantly solves its batch's similarity transform (gathers are
// L2-hits after the first block per batch; Newton runs lockstep on all threads),
// then applies it to its 512-pixel chunk (2 float4-triples per thread).
// DRAM streaming loads are issued BEFORE Newton so their latency hides under it.
__global__ void __launch_bounds__(256) fused_kernel(const float* __restrict__ Offset,
                                                    const float* __restrict__ Posmap,
                                                    const float* __restrict__ meanp,
                                                    const int* __restrict__ uv32,
                                                    float* __restrict__ out)
{
    const int b     = blockIdx.x >> 5;
    const int chunk = blockIdx.x & 31;
    const int tid   = threadIdx.x;
    const int wid   = tid >> 5;
    const int lane  = tid & 31;

    __shared__ float src[NKPT][3];
    __shared__ float dst[NKPT][3];
    __shared__ float red[3][9];     // per-warp partials (warps 0-2 active)
    __shared__ float bc[16];        // 0:s  1-3:mA  4-6:mB  7-15:H (row-major [i][j])
    __shared__ int s_any;

    if (tid == 0) s_any = 0;
    __syncthreads();

    // uv dtype sniff (int64 little-endian => all odd 32-bit words are zero).
    if (tid < NKPT) {
        if (uv32[2*tid + 1] != 0) atomicOr(&s_any, 1);
    }
    __syncthreads();
    const int is64 = (s_any == 0);

    // Gather keypoints: threads 0..203 handle one (kpt, channel) pair each.
    if (tid < 3 * NKPT) {
        const int k = tid / 3;
        const int c = tid - 3 * k;
        int u, v;
        if (is64) { u = uv32[4*k]; v = uv32[4*k + 2]; }
        else      { u = uv32[2*k]; v = uv32[2*k + 1]; }
        const int idx = u * WDIM + v;
        const size_t off = (size_t)b * 3 * HWSZ + (size_t)c * HWSZ + idx;
        float o = Offset[off];
        float d = Posmap[off];
        float m = meanp[(size_t)c * HWSZ + idx];
        dst[k][c] = d;
        src[k][c] = fmaf(OFFSET_SCALE, o, m);
    }
    __syncthreads();

    // Round 1: reduce {d1, d2, sum(src xyz), sum(dst xyz)} = 8 quantities.
    if (wid < 3) {
        float v[8] = {0,0,0,0,0,0,0,0};
        if (tid < NKPT) {
            float rx = src[33][0], ry = src[33][1], rz = src[33][2];
            float qx = dst[33][0], qy = dst[33][1], qz = dst[33][2];
            float dx = src[tid][0]-rx, dy = src[tid][1]-ry, dz = src[tid][2]-rz;
            float ex = dst[tid][0]-qx, ey = dst[tid][1]-qy, ez = dst[tid][2]-qz;
            v[0] = sqrtf(dx*dx + dy*dy + dz*dz);
            v[1] = sqrtf(ex*ex + ey*ey + ez*ez);
            v[2] = src[tid][0]; v[3] = src[tid][1]; v[4] = src[tid][2];
            v[5] = dst[tid][0]; v[6] = dst[tid][1]; v[7] = dst[tid][2];
        }
        #pragma unroll
        for (int q = 0; q < 8; ++q) v[q] = warp_sum(v[q]);
        if (lane == 0) {
            #pragma unroll
            for (int q = 0; q < 8; ++q) red[wid][q] = v[q];
        }
    }
    __syncthreads();
    if (tid == 0) {
        float t[8];
        #pragma unroll
        for (int q = 0; q < 8; ++q) t[q] = red[0][q] + red[1][q] + red[2][q];
        const float s = t[1] / t[0];
        const float inv_n = 1.0f / (float)NKPT;
        bc[0] = s;
        bc[1] = t[2] * s * inv_n;  bc[2] = t[3] * s * inv_n;  bc[3] = t[4] * s * inv_n;
        bc[4] = t[5] * inv_n;      bc[5] = t[6] * inv_n;      bc[6] = t[7] * inv_n;
    }
    __syncthreads();

    // Round 2: H[i][j] = sum_k (s*src[k][i]-mA[i]) * (dst[k][j]-mB[j]).
    if (wid < 3) {
        const float s = bc[0];
        const float mA0 = bc[1], mA1 = bc[2], mA2 = bc[3];
        const float mB0 = bc[4], mB1 = bc[5], mB2 = bc[6];
        float h[9] = {0,0,0,0,0,0,0,0,0};
        if (tid < NKPT) {
            float a0 = fmaf(s, src[tid][0], -mA0);
            float a1 = fmaf(s, src[tid][1], -mA1);
            float a2 = fmaf(s, src[tid][2], -mA2);
            float b0 = dst[tid][0] - mB0;
            float b1 = dst[tid][1] - mB1;
            float b2 = dst[tid][2] - mB2;
            h[0] = a0*b0; h[1] = a0*b1; h[2] = a0*b2;
            h[3] = a1*b0; h[4] = a1*b1; h[5] = a1*b2;
            h[6] = a2*b0; h[7] = a2*b1; h[8] = a2*b2;
        }
        #pragma unroll
        for (int q = 0; q < 9; ++q) h[q] = warp_sum(h[q]);
        if (lane == 0) {
            #pragma unroll
            for (int q = 0; q < 9; ++q) red[wid][q] = h[q];
        }
    }
    __syncthreads();
    if (tid == 0) {
        #pragma unroll
        for (int q = 0; q < 9; ++q) bc[7 + q] = red[0][q] + red[1][q] + red[2][q];
    }
    __syncthreads();

    // ---- Issue DRAM streaming loads NOW (latency hides under Newton) ----
    const int p0    = (chunk << 9) | tid;   // chunk*512 + tid
    const int p1    = p0 + 256;
    const int plane = HWSZ / 4;             // 16384
    const float4* ob = (const float4*)Offset + (size_t)b * 3 * plane;
    float4 x0 = __ldcs(ob + p0);
    float4 x1 = __ldcs(ob + p1);
    float4 y0 = __ldcs(ob + p0 + plane);
    float4 y1 = __ldcs(ob + p1 + plane);
    float4 z0 = __ldcs(ob + p0 + 2 * plane);
    float4 z1 = __ldcs(ob + p1 + 2 * plane);

    // ---- Newton polar iteration (all threads, redundant & lockstep) ----
    // Reference R = V U^T (H = U S Vh) == polar factor of H^T; det-sign preserving.
    const float s   = bc[0];
    const float mA0 = bc[1], mA1 = bc[2], mA2 = bc[3];
    const float mB0 = bc[4], mB1 = bc[5], mB2 = bc[6];

    float X[9];
    X[0]=bc[7+0]; X[1]=bc[7+3]; X[2]=bc[7+6];   // X = H^T
    X[3]=bc[7+1]; X[4]=bc[7+4]; X[5]=bc[7+7];
    X[6]=bc[7+2]; X[7]=bc[7+5]; X[8]=bc[7+8];

    float Y[9];
    for (int it = 0; it < 30; ++it) {
        inv3_transpose(X, Y);
        float nx = 0.f, ny = 0.f;
        #pragma unroll
        for (int i = 0; i < 9; ++i) { nx += X[i]*X[i]; ny += Y[i]*Y[i]; }
        float g  = sqrtf(sqrtf(ny / nx));
        float ig = 1.0f / g;
        float diff = 0.f;
        #pragma unroll
        for (int i = 0; i < 9; ++i) {
            float xn = 0.5f * (g * X[i] + ig * Y[i]);
            float d  = xn - X[i];
            diff += d * d;
            X[i] = xn;
        }
        if (diff <= 1e-14f * nx) break;   // uniform across block (same data)
    }

    // Params: scaled R (row-major [j][i]) and T.
    const float R00 = X[0]*s, R01 = X[1]*s, R02 = X[2]*s;
    const float R10 = X[3]*s, R11 = X[4]*s, R12 = X[5]*s;
    const float R20 = X[6]*s, R21 = X[7]*s, R22 = X[8]*s;
    const float T0 = mB0 - (mA0*X[0] + mA1*X[1] + mA2*X[2]);
    const float T1 = mB1 - (mA0*X[3] + mA1*X[4] + mA2*X[5]);
    const float T2 = mB2 - (mA0*X[6] + mA1*X[7] + mA2*X[8]);

    // ---- L2-resident mean loads (short latency; issued late to save regs) ----
    const float4* mp = (const float4*)meanp;
    float4 mx0 = __ldg(mp + p0);
    float4 mx1 = __ldg(mp + p1);
    float4 my0 = __ldg(mp + p0 + plane);
    float4 my1 = __ldg(mp + p1 + plane);
    float4 mz0 = __ldg(mp + p0 + 2 * plane);
    float4 mz1 = __ldg(mp + p1 + 2 * plane);

    float4* outb = (float4*)out + (size_t)b * 3 * plane;

    #pragma unroll
    for (int u = 0; u < 2; ++u) {
        const float4 xx = u ? x1 : x0, yy = u ? y1 : y0, zz = u ? z1 : z0;
        const float4 mx = u ? mx1 : mx0, my = u ? my1 : my0, mz = u ? mz1 : mz0;
        const int p = u ? p1 : p0;

        float o0[4], o1[4], o2[4];
        o0[0]=fmaf(OFFSET_SCALE,xx.x,mx.x); o0[1]=fmaf(OFFSET_SCALE,xx.y,mx.y);
        o0[2]=fmaf(OFFSET_SCALE,xx.z,mx.z); o0[3]=fmaf(OFFSET_SCALE,xx.w,mx.w);
        o1[0]=fmaf(OFFSET_SCALE,yy.x,my.x); o1[1]=fmaf(OFFSET_SCALE,yy.y,my.y);
        o1[2]=fmaf(OFFSET_SCALE,yy.z,my.z); o1[3]=fmaf(OFFSET_SCALE,yy.w,my.w);
        o2[0]=fmaf(OFFSET_SCALE,zz.x,mz.x); o2[1]=fmaf(OFFSET_SCALE,zz.y,mz.y);
        o2[2]=fmaf(OFFSET_SCALE,zz.z,mz.z); o2[3]=fmaf(OFFSET_SCALE,zz.w,mz.w);

        float4 r0, r1, r2;
        float* pr0 = &r0.x; float* pr1 = &r1.x; float* pr2 = &r2.x;
        #pragma unroll
        for (int l = 0; l < 4; ++l) {
            pr0[l] = fmaf(R00, o0[l], fmaf(R01, o1[l], fmaf(R02, o2[l], T0)));
            pr1[l] = fmaf(R10, o0[l], fmaf(R11, o1[l], fmaf(R12, o2[l], T1)));
            pr2[l] = fmaf(R20, o0[l], fmaf(R21, o1[l], fmaf(R22, o2[l], T2)));
        }

        __stcs(outb + p,             r0);
        __stcs(outb + p + plane,     r1);
        __stcs(outb + p + 2 * plane, r2);
    }
}

extern "C" void kernel_launch(void* const* d_in, const int* in_sizes, int n_in,
                              void* d_out, int out_size)
{
    const float* Offset = (const float*)d_in[0];
    const float* Posmap = (const float*)d_in[1];
    const float* meanp  = (const float*)d_in[2];
    const int*   uv     = (const int*)d_in[3];
    float* out = (float*)d_out;

    const int B = in_sizes[0] / (3 * HWSZ);

    fused_kernel<<<B * 32, 256>>>(Offset, Posmap, meanp, uv, out);
}